// round 2
// baseline (speedup 1.0000x reference)
#include <cuda_runtime.h>
#include <math.h>

#define TOKENS 1024
#define HD 2880            // hidden dim H
#define E_NUM 16
#define I_DIM 2880
#define GU (2*I_DIM)       // 5760 interleaved gate/up cols
#define TOPK 4
#define NPAIR (TOKENS*TOPK)
#define ALPHA 1.702f
#define LIMIT 7.0f

// Scratch: __device__ globals (allocation inside kernel_launch is forbidden).
__device__ float g_act[NPAIR * I_DIM];    // 47 MB: activation per (token,expert) pair
__device__ float g_outp[NPAIR * HD];      // 47 MB: per-pair expert output (no bias/prob)
__device__ int   g_cnt[E_NUM];            // tokens per expert
__device__ int   g_list[E_NUM * TOKENS];  // pair ids gathered per expert
__device__ int   g_pe[NPAIR];             // expert id per pair
__device__ float g_pp[NPAIR];             // routing prob per pair

__global__ void k_init() {
    if (threadIdx.x < E_NUM) g_cnt[threadIdx.x] = 0;
}

// Router: one block per token, 128 threads. logits = x @ rw^T + rb, top-4, softmax.
__global__ void k_router(const float* __restrict__ flat,
                         const float* __restrict__ rw,
                         const float* __restrict__ rb) {
    int t   = blockIdx.x;
    int tid = threadIdx.x;
    const float* x = flat + (size_t)t * HD;

    float part[E_NUM];
    #pragma unroll
    for (int e = 0; e < E_NUM; e++) part[e] = 0.f;

    for (int h = tid; h < HD; h += 128) {
        float xv = x[h];
        #pragma unroll
        for (int e = 0; e < E_NUM; e++)
            part[e] += xv * rw[e * HD + h];
    }

    __shared__ float sm[E_NUM][128];
    #pragma unroll
    for (int e = 0; e < E_NUM; e++) sm[e][tid] = part[e];
    __syncthreads();

    if (tid < E_NUM) {
        float s = 0.f;
        for (int j = 0; j < 128; j++) s += sm[tid][j];
        sm[tid][0] = s + rb[tid];
    }
    __syncthreads();

    if (tid == 0) {
        float v[E_NUM];
        #pragma unroll
        for (int e = 0; e < E_NUM; e++) v[e] = sm[e][0];
        int   idx[TOPK];
        float val[TOPK];
        #pragma unroll
        for (int k = 0; k < TOPK; k++) {
            int bi = 0; float bv = -1e30f;
            #pragma unroll
            for (int e = 0; e < E_NUM; e++)
                if (v[e] > bv) { bv = v[e]; bi = e; }   // first index on ties, like jax top_k
            idx[k] = bi; val[k] = bv; v[bi] = -1e30f;
        }
        float m = val[0], s = 0.f, p[TOPK];
        #pragma unroll
        for (int k = 0; k < TOPK; k++) { p[k] = __expf(val[k] - m); s += p[k]; }
        float inv = 1.f / s;
        #pragma unroll
        for (int k = 0; k < TOPK; k++) {
            int pid = t * TOPK + k;
            g_pe[pid] = idx[k];
            g_pp[pid] = p[k] * inv;
            int slot = atomicAdd(&g_cnt[idx[k]], 1);
            g_list[idx[k] * TOKENS + slot] = pid;
        }
    }
}

// Pass A: per expert, gathered-token GEMM X[n,2880] @ w1e^T -> gu, fused activation.
// Block tile: 64 tokens x 128 gu cols (= 64 i values). 256 threads, 4x8 microtile.
__global__ void __launch_bounds__(256)
k_ffn1(const float* __restrict__ flat,
       const float* __restrict__ w1,
       const float* __restrict__ b1) {
    const int e = blockIdx.z;
    const int n = g_cnt[e];
    const int row0 = blockIdx.y * 64;
    if (row0 >= n) return;
    const int i0 = blockIdx.x * 64;     // i tile
    const int c0 = 2 * i0;              // gu col base (128 cols)

    __shared__ int   s_pid[64];
    __shared__ int   s_tok[64];
    __shared__ float As[64][16];        // row-major (token x k)
    __shared__ float Bs[16][128];       // k-major (k x gu-col)

    const int tid = threadIdx.x;
    if (tid < 64) {
        int slot = row0 + tid;
        int pid  = (slot < n) ? g_list[e * TOKENS + slot] : -1;
        s_pid[tid] = pid;
        s_tok[tid] = (pid >= 0) ? (pid >> 2) : 0;
    }
    __syncthreads();

    const int tx = tid & 15;   // cols: tx*8 + j
    const int ty = tid >> 4;   // rows: ty*4 + i
    float acc[4][8];
    #pragma unroll
    for (int i = 0; i < 4; i++)
        #pragma unroll
        for (int j = 0; j < 8; j++) acc[i][j] = 0.f;

    const size_t w1e = (size_t)e * GU * HD;
    const int ar = tid >> 2, akq = tid & 3;   // A tile load: row, float4-slot

    for (int k0 = 0; k0 < HD; k0 += 16) {
        float4 av = *(const float4*)(flat + (size_t)s_tok[ar] * HD + k0 + akq * 4);
        *(float4*)&As[ar][akq * 4] = av;
        #pragma unroll
        for (int l = 0; l < 2; l++) {
            int f = tid + l * 256;
            int c = f >> 2, kq = f & 3;
            float4 bv = *(const float4*)(w1 + w1e + (size_t)(c0 + c) * HD + k0 + kq * 4);
            Bs[kq * 4 + 0][c] = bv.x;
            Bs[kq * 4 + 1][c] = bv.y;
            Bs[kq * 4 + 2][c] = bv.z;
            Bs[kq * 4 + 3][c] = bv.w;
        }
        __syncthreads();
        #pragma unroll
        for (int k = 0; k < 16; k++) {
            float a[4];
            #pragma unroll
            for (int i = 0; i < 4; i++) a[i] = As[ty * 4 + i][k];
            float4 bA = *(const float4*)&Bs[k][tx * 8];
            float4 bB = *(const float4*)&Bs[k][tx * 8 + 4];
            float b[8] = { bA.x, bA.y, bA.z, bA.w, bB.x, bB.y, bB.z, bB.w };
            #pragma unroll
            for (int i = 0; i < 4; i++)
                #pragma unroll
                for (int j = 0; j < 8; j++)
                    acc[i][j] += a[i] * b[j];
        }
        __syncthreads();
    }

    // Epilogue: bias + clamp + gated activation, store act (one i per col pair).
    float bb[8];
    #pragma unroll
    for (int j = 0; j < 8; j++) bb[j] = b1[(size_t)e * GU + c0 + tx * 8 + j];

    #pragma unroll
    for (int i = 0; i < 4; i++) {
        int r = ty * 4 + i;
        int pid = s_pid[r];
        if (pid < 0) continue;
        float* arow = g_act + (size_t)pid * I_DIM;
        #pragma unroll
        for (int jj = 0; jj < 4; jj++) {
            float gate = acc[i][jj * 2]     + bb[jj * 2];
            float up   = acc[i][jj * 2 + 1] + bb[jj * 2 + 1];
            gate = fminf(gate, LIMIT);
            up   = fminf(fmaxf(up, -LIMIT), LIMIT);
            float sg = 1.f / (1.f + __expf(-ALPHA * gate));
            arow[i0 + tx * 4 + jj] = (up + 1.f) * (gate * sg);
        }
    }
}

// Pass B: per expert, act[n,2880] @ w2e^T -> per-pair output. 64x64 tile, 4x4 microtile.
__global__ void __launch_bounds__(256)
k_ffn2(const float* __restrict__ w2) {
    const int e = blockIdx.z;
    const int n = g_cnt[e];
    const int row0 = blockIdx.y * 64;
    if (row0 >= n) return;
    const int h0 = blockIdx.x * 64;

    __shared__ int   s_pid[64];
    __shared__ float As[64][16];
    __shared__ float Bs[16][64];

    const int tid = threadIdx.x;
    if (tid < 64) {
        int slot = row0 + tid;
        s_pid[tid] = (slot < n) ? g_list[e * TOKENS + slot] : -1;
    }
    __syncthreads();

    const int tx = tid & 15;   // cols: tx*4 + j
    const int ty = tid >> 4;   // rows: ty*4 + i
    float acc[4][4];
    #pragma unroll
    for (int i = 0; i < 4; i++)
        #pragma unroll
        for (int j = 0; j < 4; j++) acc[i][j] = 0.f;

    const size_t w2e = (size_t)e * HD * I_DIM;
    const int ar = tid >> 2, akq = tid & 3;

    for (int k0 = 0; k0 < I_DIM; k0 += 16) {
        int pr = s_pid[ar];
        const float* arow = g_act + (size_t)(pr < 0 ? 0 : pr) * I_DIM;
        float4 av = *(const float4*)(arow + k0 + akq * 4);
        *(float4*)&As[ar][akq * 4] = av;
        {
            int c = tid >> 2, kq = tid & 3;
            float4 bv = *(const float4*)(w2 + w2e + (size_t)(h0 + c) * I_DIM + k0 + kq * 4);
            Bs[kq * 4 + 0][c] = bv.x;
            Bs[kq * 4 + 1][c] = bv.y;
            Bs[kq * 4 + 2][c] = bv.z;
            Bs[kq * 4 + 3][c] = bv.w;
        }
        __syncthreads();
        #pragma unroll
        for (int k = 0; k < 16; k++) {
            float a[4];
            #pragma unroll
            for (int i = 0; i < 4; i++) a[i] = As[ty * 4 + i][k];
            float4 bv = *(const float4*)&Bs[k][tx * 4];
            float b[4] = { bv.x, bv.y, bv.z, bv.w };
            #pragma unroll
            for (int i = 0; i < 4; i++)
                #pragma unroll
                for (int j = 0; j < 4; j++)
                    acc[i][j] += a[i] * b[j];
        }
        __syncthreads();
    }

    #pragma unroll
    for (int i = 0; i < 4; i++) {
        int r = ty * 4 + i;
        int pid = s_pid[r];
        if (pid < 0) continue;
        float* orow = g_outp + (size_t)pid * HD;
        float4 v = make_float4(acc[i][0], acc[i][1], acc[i][2], acc[i][3]);
        *(float4*)(orow + h0 + tx * 4) = v;
    }
}

// Combine: out[t,h] = sum_k p_k * (outp_k[h] + b2[e_k][h]); fixed k order -> deterministic.
__global__ void k_combine(const float* __restrict__ b2, float* __restrict__ out) {
    int t = blockIdx.x;
    __shared__ int   se[TOPK];
    __shared__ float sp[TOPK];
    if (threadIdx.x < TOPK) {
        se[threadIdx.x] = g_pe[t * TOPK + threadIdx.x];
        sp[threadIdx.x] = g_pp[t * TOPK + threadIdx.x];
    }
    __syncthreads();
    for (int h = threadIdx.x; h < HD; h += blockDim.x) {
        float s = 0.f;
        #pragma unroll
        for (int k = 0; k < TOPK; k++)
            s += sp[k] * (g_outp[(size_t)(t * TOPK + k) * HD + h] + b2[(size_t)se[k] * HD + h]);
        out[(size_t)t * HD + h] = s;
    }
}

extern "C" void kernel_launch(void* const* d_in, const int* in_sizes, int n_in,
                              void* d_out, int out_size) {
    const float* hidden = (const float*)d_in[0];
    const float* rw     = (const float*)d_in[1];
    const float* rb     = (const float*)d_in[2];
    const float* w1     = (const float*)d_in[3];
    const float* b1     = (const float*)d_in[4];
    const float* w2     = (const float*)d_in[5];
    const float* b2     = (const float*)d_in[6];
    float* out = (float*)d_out;

    k_init<<<1, E_NUM>>>();
    k_router<<<TOKENS, 128>>>(hidden, rw, rb);

    dim3 gA(I_DIM / 64, TOKENS / 64, E_NUM);   // 45 x 16 x 16 (row tiles past count exit early)
    k_ffn1<<<gA, 256>>>(hidden, w1, b1);

    dim3 gB(HD / 64, TOKENS / 64, E_NUM);      // 45 x 16 x 16
    k_ffn2<<<gB, 256>>>(w2);

    k_combine<<<TOKENS, 256>>>(b2, out);
}

// round 5
// speedup vs baseline: 2.1059x; 2.1059x over previous
#include <cuda_runtime.h>
#include <cuda_bf16.h>
#include <math.h>
#include <stdint.h>

#define TOKENS 1024
#define HD 2880
#define E_NUM 16
#define I_DIM 2880
#define GU (2*I_DIM)
#define TOPK 4
#define NPAIR (TOKENS*TOPK)
#define ALPHA 1.702f
#define LIMIT 7.0f
#define BK 32                    // fp32 K elems per smem stage
#define KIT1 (HD/BK)             // 90
#define KIT2 (I_DIM/BK)          // 90
#define ROWB 80                  // smem row pitch bytes: 32 bf16 (64B) + 16B pad -> conflict-free ldmatrix

// ---------------- scratch ----------------
__device__ float g_act[NPAIR * I_DIM];
__device__ float g_outp[NPAIR * HD];
__device__ int   g_cnt[E_NUM];
__device__ int   g_list[E_NUM * TOKENS];
__device__ int   g_pe[NPAIR];
__device__ float g_pp[NPAIR];

// ---------------- helpers ----------------
__device__ __forceinline__ uint32_t smem_u32(const void* p) {
    uint32_t a;
    asm("{ .reg .u64 t; cvta.to.shared.u64 t, %1; cvt.u32.u64 %0, t; }" : "=r"(a) : "l"(p));
    return a;
}
#define LDSM4(r, addr) \
    asm volatile("ldmatrix.sync.aligned.m8n8.x4.shared.b16 {%0,%1,%2,%3}, [%4];" \
        : "=r"((r)[0]), "=r"((r)[1]), "=r"((r)[2]), "=r"((r)[3]) : "r"(addr))
#define MMA16816(d, a, b0, b1) \
    asm volatile("mma.sync.aligned.m16n8k16.row.col.f32.bf16.bf16.f32 " \
        "{%0,%1,%2,%3}, {%4,%5,%6,%7}, {%8,%9}, {%0,%1,%2,%3};" \
        : "+f"((d)[0]), "+f"((d)[1]), "+f"((d)[2]), "+f"((d)[3]) \
        : "r"((a)[0]), "r"((a)[1]), "r"((a)[2]), "r"((a)[3]), "r"(b0), "r"(b1))

// Split a float4 into packed bf16 hi pair-words and lo pair-words.
__device__ __forceinline__ void split4(float4 v, uint32_t& h01, uint32_t& h23,
                                       uint32_t& l01, uint32_t& l23) {
    asm("cvt.rn.bf16x2.f32 %0, %1, %2;" : "=r"(h01) : "f"(v.y), "f"(v.x));
    asm("cvt.rn.bf16x2.f32 %0, %1, %2;" : "=r"(h23) : "f"(v.w), "f"(v.z));
    float f0 = __uint_as_float(h01 << 16);
    float f1 = __uint_as_float(h01 & 0xFFFF0000u);
    float f2 = __uint_as_float(h23 << 16);
    float f3 = __uint_as_float(h23 & 0xFFFF0000u);
    asm("cvt.rn.bf16x2.f32 %0, %1, %2;" : "=r"(l01) : "f"(v.y - f1), "f"(v.x - f0));
    asm("cvt.rn.bf16x2.f32 %0, %1, %2;" : "=r"(l23) : "f"(v.w - f3), "f"(v.z - f2));
}

// Stage 16 fp32 (4 float4) from src into hi/lo smem at byte offset `off` (contiguous 32B).
__device__ __forceinline__ void stage16(const float* __restrict__ src,
                                        unsigned char* smh, unsigned char* sml, uint32_t off) {
    const float4* s4 = (const float4*)src;
    #pragma unroll
    for (int q = 0; q < 4; q++) {
        uint32_t h01, h23, l01, l23;
        split4(s4[q], h01, h23, l01, l23);
        *(uint2*)(smh + off + q * 8) = make_uint2(h01, h23);
        *(uint2*)(sml + off + q * 8) = make_uint2(l01, l23);
    }
}
__device__ __forceinline__ void stage16_zero(unsigned char* smh, unsigned char* sml, uint32_t off) {
    #pragma unroll
    for (int q = 0; q < 4; q++) {
        *(uint2*)(smh + off + q * 8) = make_uint2(0u, 0u);
        *(uint2*)(sml + off + q * 8) = make_uint2(0u, 0u);
    }
}

// ---------------- small kernels ----------------
__global__ void k_init() {
    if (threadIdx.x < E_NUM) g_cnt[threadIdx.x] = 0;
}

__global__ void k_router(const float* __restrict__ flat,
                         const float* __restrict__ rw,
                         const float* __restrict__ rb) {
    int t = blockIdx.x, tid = threadIdx.x;
    const float* x = flat + (size_t)t * HD;
    float part[E_NUM];
    #pragma unroll
    for (int e = 0; e < E_NUM; e++) part[e] = 0.f;
    for (int h = tid; h < HD; h += 128) {
        float xv = x[h];
        #pragma unroll
        for (int e = 0; e < E_NUM; e++) part[e] += xv * rw[e * HD + h];
    }
    __shared__ float sm[E_NUM][128];
    #pragma unroll
    for (int e = 0; e < E_NUM; e++) sm[e][tid] = part[e];
    __syncthreads();
    if (tid < E_NUM) {
        float s = 0.f;
        for (int j = 0; j < 128; j++) s += sm[tid][j];
        sm[tid][0] = s + rb[tid];
    }
    __syncthreads();
    if (tid == 0) {
        float v[E_NUM];
        #pragma unroll
        for (int e = 0; e < E_NUM; e++) v[e] = sm[e][0];
        int idx[TOPK]; float val[TOPK];
        #pragma unroll
        for (int k = 0; k < TOPK; k++) {
            int bi = 0; float bv = -1e30f;
            #pragma unroll
            for (int e = 0; e < E_NUM; e++)
                if (v[e] > bv) { bv = v[e]; bi = e; }
            idx[k] = bi; val[k] = bv; v[bi] = -1e30f;
        }
        float m = val[0], s = 0.f, p[TOPK];
        #pragma unroll
        for (int k = 0; k < TOPK; k++) { p[k] = __expf(val[k] - m); s += p[k]; }
        float inv = 1.f / s;
        #pragma unroll
        for (int k = 0; k < TOPK; k++) {
            int pid = t * TOPK + k;
            g_pe[pid] = idx[k];
            g_pp[pid] = p[k] * inv;
            int slot = atomicAdd(&g_cnt[idx[k]], 1);
            g_list[idx[k] * TOKENS + slot] = pid;
        }
    }
}

// ---------------- FFN1: 128x128 tile, split-bf16 mma.sync ----------------
__global__ void __launch_bounds__(256)
k_ffn1(const float* __restrict__ flat,
       const float* __restrict__ w1,
       const float* __restrict__ b1) {
    const int e = blockIdx.z;
    const int n = g_cnt[e];
    const int row0 = blockIdx.x * 128;
    if (row0 >= n) return;
    const int c0 = blockIdx.y * 128;

    __shared__ __align__(16) unsigned char sAh[128 * ROWB], sAl[128 * ROWB];
    __shared__ __align__(16) unsigned char sBh[128 * ROWB], sBl[128 * ROWB];
    __shared__ int s_pid[128];
    __shared__ int s_tok[128];

    const int tid  = threadIdx.x;
    const int lane = tid & 31;
    const int wrp  = tid >> 5;
    const int wm   = wrp & 3;     // 4 m-groups of 32 rows
    const int wn   = wrp >> 2;    // 2 n-groups of 64 cols

    {
        int slot = row0 + tid;
        int pid  = (slot < n && tid < 128) ? g_list[e * TOKENS + slot] : -1;
        if (tid < 128) { s_pid[tid] = pid; s_tok[tid] = (pid >= 0) ? (pid >> 2) : 0; }
    }
    __syncthreads();

    const int srow = tid >> 1, sseg = tid & 1;
    const uint32_t soff = (uint32_t)srow * ROWB + (uint32_t)sseg * 32;
    const float* myA = flat + (size_t)s_tok[srow] * HD + sseg * 16;
    const float* myB = w1 + (size_t)e * GU * HD + (size_t)(c0 + srow) * HD + sseg * 16;

    // ldmatrix addresses
    const uint32_t uAh = smem_u32(sAh), uAl = smem_u32(sAl);
    const uint32_t uBh = smem_u32(sBh), uBl = smem_u32(sBl);
    uint32_t aoffs = (uint32_t)(wm * 32 + (lane & 15)) * ROWB + ((lane >> 4) & 1) * 16;
    uint32_t boffs = (uint32_t)(wn * 64 + ((lane >> 4) & 1) * 8 + (lane & 7)) * ROWB
                   + ((lane >> 3) & 1) * 16;

    float acc[2][8][4];
    #pragma unroll
    for (int mt = 0; mt < 2; mt++)
        #pragma unroll
        for (int nt = 0; nt < 8; nt++)
            #pragma unroll
            for (int q = 0; q < 4; q++) acc[mt][nt][q] = 0.f;

    for (int it = 0; it < KIT1; it++) {
        __syncthreads();
        stage16(myA + it * BK, sAh, sAl, soff);
        stage16(myB + it * BK, sBh, sBl, soff);
        __syncthreads();

        #pragma unroll
        for (int ks = 0; ks < 2; ks++) {
            const uint32_t kb = ks * 32;
            uint32_t aH[2][4], aL[2][4], bH[4][4], bL[4][4];
            #pragma unroll
            for (int mt = 0; mt < 2; mt++) {
                LDSM4(aH[mt], uAh + aoffs + (uint32_t)mt * 16 * ROWB + kb);
                LDSM4(aL[mt], uAl + aoffs + (uint32_t)mt * 16 * ROWB + kb);
            }
            #pragma unroll
            for (int p = 0; p < 4; p++) {
                LDSM4(bH[p], uBh + boffs + (uint32_t)p * 16 * ROWB + kb);
                LDSM4(bL[p], uBl + boffs + (uint32_t)p * 16 * ROWB + kb);
            }
            #pragma unroll
            for (int mt = 0; mt < 2; mt++)
                #pragma unroll
                for (int nt = 0; nt < 8; nt++) {
                    const int p = nt >> 1, o = (nt & 1) * 2;
                    MMA16816(acc[mt][nt], aH[mt], bH[p][o], bH[p][o + 1]);
                    MMA16816(acc[mt][nt], aH[mt], bL[p][o], bL[p][o + 1]);
                    MMA16816(acc[mt][nt], aL[mt], bH[p][o], bH[p][o + 1]);
                }
        }
    }

    // epilogue: bias + clamp + gated activation -> g_act
    const float* b1g = b1 + (size_t)e * GU + c0;
    const int i0 = c0 >> 1;
    const int l4 = lane >> 2, lm = lane & 3;
    #pragma unroll
    for (int mt = 0; mt < 2; mt++) {
        const int mA = wm * 32 + mt * 16 + l4;
        const int pid0 = s_pid[mA], pid1 = s_pid[mA + 8];
        float* a0 = g_act + (size_t)(pid0 < 0 ? 0 : pid0) * I_DIM;
        float* a1 = g_act + (size_t)(pid1 < 0 ? 0 : pid1) * I_DIM;
        #pragma unroll
        for (int nt = 0; nt < 8; nt++) {
            const int nbase = wn * 64 + nt * 8 + 2 * lm;
            float2 bb = *(const float2*)(b1g + nbase);
            const int ii = i0 + (nbase >> 1);
            {
                float gate = acc[mt][nt][0] + bb.x;
                float up   = acc[mt][nt][1] + bb.y;
                gate = fminf(gate, LIMIT);
                up   = fminf(fmaxf(up, -LIMIT), LIMIT);
                float sg = 1.f / (1.f + __expf(-ALPHA * gate));
                if (pid0 >= 0) a0[ii] = (up + 1.f) * (gate * sg);
            }
            {
                float gate = acc[mt][nt][2] + bb.x;
                float up   = acc[mt][nt][3] + bb.y;
                gate = fminf(gate, LIMIT);
                up   = fminf(fmaxf(up, -LIMIT), LIMIT);
                float sg = 1.f / (1.f + __expf(-ALPHA * gate));
                if (pid1 >= 0) a1[ii] = (up + 1.f) * (gate * sg);
            }
        }
    }
}

// ---------------- FFN2: 128x128 tile (last n-tile partial), split-bf16 mma.sync ----------------
__global__ void __launch_bounds__(256)
k_ffn2(const float* __restrict__ w2) {
    const int e = blockIdx.z;
    const int n = g_cnt[e];
    const int row0 = blockIdx.x * 128;
    if (row0 >= n) return;
    const int h0 = blockIdx.y * 128;

    __shared__ __align__(16) unsigned char sAh[128 * ROWB], sAl[128 * ROWB];
    __shared__ __align__(16) unsigned char sBh[128 * ROWB], sBl[128 * ROWB];
    __shared__ int s_pid[128];

    const int tid  = threadIdx.x;
    const int lane = tid & 31;
    const int wrp  = tid >> 5;
    const int wm   = wrp & 3;
    const int wn   = wrp >> 2;

    if (tid < 128) {
        int slot = row0 + tid;
        s_pid[tid] = (slot < n) ? g_list[e * TOKENS + slot] : -1;
    }
    __syncthreads();

    const int srow = tid >> 1, sseg = tid & 1;
    const uint32_t soff = (uint32_t)srow * ROWB + (uint32_t)sseg * 32;
    const int apid = (s_pid[srow] < 0) ? 0 : s_pid[srow];
    const float* myA = g_act + (size_t)apid * I_DIM + sseg * 16;
    const int bcol = h0 + srow;
    const bool bok = (bcol < HD);
    const float* myB = w2 + (size_t)e * HD * I_DIM + (size_t)(bok ? bcol : 0) * I_DIM + sseg * 16;

    const uint32_t uAh = smem_u32(sAh), uAl = smem_u32(sAl);
    const uint32_t uBh = smem_u32(sBh), uBl = smem_u32(sBl);
    uint32_t aoffs = (uint32_t)(wm * 32 + (lane & 15)) * ROWB + ((lane >> 4) & 1) * 16;
    uint32_t boffs = (uint32_t)(wn * 64 + ((lane >> 4) & 1) * 8 + (lane & 7)) * ROWB
                   + ((lane >> 3) & 1) * 16;

    float acc[2][8][4];
    #pragma unroll
    for (int mt = 0; mt < 2; mt++)
        #pragma unroll
        for (int nt = 0; nt < 8; nt++)
            #pragma unroll
            for (int q = 0; q < 4; q++) acc[mt][nt][q] = 0.f;

    for (int it = 0; it < KIT2; it++) {
        __syncthreads();
        stage16(myA + it * BK, sAh, sAl, soff);
        if (bok) stage16(myB + it * BK, sBh, sBl, soff);
        else     stage16_zero(sBh, sBl, soff);
        __syncthreads();

        #pragma unroll
        for (int ks = 0; ks < 2; ks++) {
            const uint32_t kb = ks * 32;
            uint32_t aH[2][4], aL[2][4], bH[4][4], bL[4][4];
            #pragma unroll
            for (int mt = 0; mt < 2; mt++) {
                LDSM4(aH[mt], uAh + aoffs + (uint32_t)mt * 16 * ROWB + kb);
                LDSM4(aL[mt], uAl + aoffs + (uint32_t)mt * 16 * ROWB + kb);
            }
            #pragma unroll
            for (int p = 0; p < 4; p++) {
                LDSM4(bH[p], uBh + boffs + (uint32_t)p * 16 * ROWB + kb);
                LDSM4(bL[p], uBl + boffs + (uint32_t)p * 16 * ROWB + kb);
            }
            #pragma unroll
            for (int mt = 0; mt < 2; mt++)
                #pragma unroll
                for (int nt = 0; nt < 8; nt++) {
                    const int p = nt >> 1, o = (nt & 1) * 2;
                    MMA16816(acc[mt][nt], aH[mt], bH[p][o], bH[p][o + 1]);
                    MMA16816(acc[mt][nt], aH[mt], bL[p][o], bL[p][o + 1]);
                    MMA16816(acc[mt][nt], aL[mt], bH[p][o], bH[p][o + 1]);
                }
        }
    }

    const int l4 = lane >> 2, lm = lane & 3;
    #pragma unroll
    for (int mt = 0; mt < 2; mt++) {
        const int mA = wm * 32 + mt * 16 + l4;
        const int pid0 = s_pid[mA], pid1 = s_pid[mA + 8];
        float* o0 = g_outp + (size_t)(pid0 < 0 ? 0 : pid0) * HD;
        float* o1 = g_outp + (size_t)(pid1 < 0 ? 0 : pid1) * HD;
        #pragma unroll
        for (int nt = 0; nt < 8; nt++) {
            const int ng = h0 + wn * 64 + nt * 8 + 2 * lm;
            if (ng < HD) {
                if (pid0 >= 0) { o0[ng] = acc[mt][nt][0]; o0[ng + 1] = acc[mt][nt][1]; }
                if (pid1 >= 0) { o1[ng] = acc[mt][nt][2]; o1[ng + 1] = acc[mt][nt][3]; }
            }
        }
    }
}

// ---------------- combine ----------------
__global__ void k_combine(const float* __restrict__ b2, float* __restrict__ out) {
    int t = blockIdx.x;
    __shared__ int   se[TOPK];
    __shared__ float sp[TOPK];
    if (threadIdx.x < TOPK) {
        se[threadIdx.x] = g_pe[t * TOPK + threadIdx.x];
        sp[threadIdx.x] = g_pp[t * TOPK + threadIdx.x];
    }
    __syncthreads();
    for (int h = threadIdx.x; h < HD; h += blockDim.x) {
        float s = 0.f;
        #pragma unroll
        for (int k = 0; k < TOPK; k++)
            s += sp[k] * (g_outp[(size_t)(t * TOPK + k) * HD + h] + b2[(size_t)se[k] * HD + h]);
        out[(size_t)t * HD + h] = s;
    }
}

extern "C" void kernel_launch(void* const* d_in, const int* in_sizes, int n_in,
                              void* d_out, int out_size) {
    const float* hidden = (const float*)d_in[0];
    const float* rw     = (const float*)d_in[1];
    const float* rb     = (const float*)d_in[2];
    const float* w1     = (const float*)d_in[3];
    const float* b1     = (const float*)d_in[4];
    const float* w2     = (const float*)d_in[5];
    const float* b2     = (const float*)d_in[6];
    float* out = (float*)d_out;

    k_init<<<1, E_NUM>>>();
    k_router<<<TOKENS, 128>>>(hidden, rw, rb);

    dim3 g1(TOKENS / 128, GU / 128, E_NUM);          // 8 x 45 x 16
    k_ffn1<<<g1, 256>>>(hidden, w1, b1);

    dim3 g2(TOKENS / 128, (HD + 127) / 128, E_NUM);  // 8 x 23 x 16
    k_ffn2<<<g2, 256>>>(w2);

    k_combine<<<TOKENS, 256>>>(b2, out);
}

// round 6
// speedup vs baseline: 2.7838x; 1.3219x over previous
#include <cuda_runtime.h>
#include <cuda_bf16.h>
#include <math.h>
#include <stdint.h>

#define TOKENS 1024
#define HD 2880
#define E_NUM 16
#define I_DIM 2880
#define GU (2*I_DIM)
#define TOPK 4
#define NPAIR (TOKENS*TOPK)
#define ALPHA 1.702f
#define LIMIT 7.0f
#define BK 32                    // fp32 K elems per stage
#define KIT1 (HD/BK)             // 90
#define KIT2 (I_DIM/BK)          // 90
#define ROWB 80                  // smem row pitch: 64B data + 16B pad (conflict-free ldmatrix)

// dyn smem: per buffer {Ah,Al,Bh,Bl} of 128*ROWB each; two buffers
#define REG  (128 * ROWB)        // 10240
#define BUFB (4 * REG)           // 40960
#define SMEM_TOT (2 * BUFB)      // 81920

// ---------------- scratch ----------------
__device__ float g_act[NPAIR * I_DIM];
__device__ float g_outp[NPAIR * HD];
__device__ int   g_cnt[E_NUM];
__device__ int   g_list[E_NUM * TOKENS];
__device__ int   g_pe[NPAIR];
__device__ float g_pp[NPAIR];

// ---------------- helpers ----------------
__device__ __forceinline__ uint32_t smem_u32(const void* p) {
    uint32_t a;
    asm("{ .reg .u64 t; cvta.to.shared.u64 t, %1; cvt.u32.u64 %0, t; }" : "=r"(a) : "l"(p));
    return a;
}
#define LDSM4(r, addr) \
    asm volatile("ldmatrix.sync.aligned.m8n8.x4.shared.b16 {%0,%1,%2,%3}, [%4];" \
        : "=r"((r)[0]), "=r"((r)[1]), "=r"((r)[2]), "=r"((r)[3]) : "r"(addr))
#define MMA16816(d, a, b0, b1) \
    asm volatile("mma.sync.aligned.m16n8k16.row.col.f32.bf16.bf16.f32 " \
        "{%0,%1,%2,%3}, {%4,%5,%6,%7}, {%8,%9}, {%0,%1,%2,%3};" \
        : "+f"((d)[0]), "+f"((d)[1]), "+f"((d)[2]), "+f"((d)[3]) \
        : "r"((a)[0]), "r"((a)[1]), "r"((a)[2]), "r"((a)[3]), "r"(b0), "r"(b1))

__device__ __forceinline__ void split4(float4 v, uint32_t& h01, uint32_t& h23,
                                       uint32_t& l01, uint32_t& l23) {
    asm("cvt.rn.bf16x2.f32 %0, %1, %2;" : "=r"(h01) : "f"(v.y), "f"(v.x));
    asm("cvt.rn.bf16x2.f32 %0, %1, %2;" : "=r"(h23) : "f"(v.w), "f"(v.z));
    float f0 = __uint_as_float(h01 << 16);
    float f1 = __uint_as_float(h01 & 0xFFFF0000u);
    float f2 = __uint_as_float(h23 << 16);
    float f3 = __uint_as_float(h23 & 0xFFFF0000u);
    asm("cvt.rn.bf16x2.f32 %0, %1, %2;" : "=r"(l01) : "f"(v.y - f1), "f"(v.x - f0));
    asm("cvt.rn.bf16x2.f32 %0, %1, %2;" : "=r"(l23) : "f"(v.w - f3), "f"(v.z - f2));
}

// store 4 float4 (16 fp32) split into hi/lo regions at byte offset off
__device__ __forceinline__ void store_split(const float4* v, unsigned char* smh,
                                            unsigned char* sml, uint32_t off) {
    #pragma unroll
    for (int q = 0; q < 4; q++) {
        uint32_t h01, h23, l01, l23;
        split4(v[q], h01, h23, l01, l23);
        *(uint2*)(smh + off + q * 8) = make_uint2(h01, h23);
        *(uint2*)(sml + off + q * 8) = make_uint2(l01, l23);
    }
}
__device__ __forceinline__ void stage16(const float* __restrict__ src,
                                        unsigned char* smh, unsigned char* sml, uint32_t off) {
    float4 v[4];
    const float4* s4 = (const float4*)src;
    #pragma unroll
    for (int q = 0; q < 4; q++) v[q] = s4[q];
    store_split(v, smh, sml, off);
}
__device__ __forceinline__ void stage16_zero(unsigned char* smh, unsigned char* sml, uint32_t off) {
    #pragma unroll
    for (int q = 0; q < 4; q++) {
        *(uint2*)(smh + off + q * 8) = make_uint2(0u, 0u);
        *(uint2*)(sml + off + q * 8) = make_uint2(0u, 0u);
    }
}

// ---------------- small kernels ----------------
__global__ void k_init() {
    if (threadIdx.x < E_NUM) g_cnt[threadIdx.x] = 0;
}

__global__ void k_router(const float* __restrict__ flat,
                         const float* __restrict__ rw,
                         const float* __restrict__ rb) {
    int t = blockIdx.x, tid = threadIdx.x;
    const float* x = flat + (size_t)t * HD;
    float part[E_NUM];
    #pragma unroll
    for (int e = 0; e < E_NUM; e++) part[e] = 0.f;
    for (int h = tid; h < HD; h += 128) {
        float xv = x[h];
        #pragma unroll
        for (int e = 0; e < E_NUM; e++) part[e] += xv * rw[e * HD + h];
    }
    __shared__ float sm[E_NUM][128];
    #pragma unroll
    for (int e = 0; e < E_NUM; e++) sm[e][tid] = part[e];
    __syncthreads();
    if (tid < E_NUM) {
        float s = 0.f;
        for (int j = 0; j < 128; j++) s += sm[tid][j];
        sm[tid][0] = s + rb[tid];
    }
    __syncthreads();
    if (tid == 0) {
        float v[E_NUM];
        #pragma unroll
        for (int e = 0; e < E_NUM; e++) v[e] = sm[e][0];
        int idx[TOPK]; float val[TOPK];
        #pragma unroll
        for (int k = 0; k < TOPK; k++) {
            int bi = 0; float bv = -1e30f;
            #pragma unroll
            for (int e = 0; e < E_NUM; e++)
                if (v[e] > bv) { bv = v[e]; bi = e; }
            idx[k] = bi; val[k] = bv; v[bi] = -1e30f;
        }
        float m = val[0], s = 0.f, p[TOPK];
        #pragma unroll
        for (int k = 0; k < TOPK; k++) { p[k] = __expf(val[k] - m); s += p[k]; }
        float inv = 1.f / s;
        #pragma unroll
        for (int k = 0; k < TOPK; k++) {
            int pid = t * TOPK + k;
            g_pe[pid] = idx[k];
            g_pp[pid] = p[k] * inv;
            int slot = atomicAdd(&g_cnt[idx[k]], 1);
            g_list[idx[k] * TOKENS + slot] = pid;
        }
    }
}

// MMA body on one staged buffer (addresses relative to u0 + cb)
#define MMA_BODY(u0, cb, aoffs, boffs, acc) \
    _Pragma("unroll") \
    for (int ks = 0; ks < 2; ks++) { \
        const uint32_t kb = (uint32_t)ks * 32u; \
        uint32_t aH[2][4], aL[2][4]; \
        _Pragma("unroll") \
        for (int mt = 0; mt < 2; mt++) { \
            LDSM4(aH[mt], (u0) + (cb) + 0 * REG + (aoffs) + (uint32_t)mt * 16 * ROWB + kb); \
            LDSM4(aL[mt], (u0) + (cb) + 1 * REG + (aoffs) + (uint32_t)mt * 16 * ROWB + kb); \
        } \
        _Pragma("unroll") \
        for (int p = 0; p < 4; p++) { \
            uint32_t bH[4], bL[4]; \
            LDSM4(bH, (u0) + (cb) + 2 * REG + (boffs) + (uint32_t)p * 16 * ROWB + kb); \
            LDSM4(bL, (u0) + (cb) + 3 * REG + (boffs) + (uint32_t)p * 16 * ROWB + kb); \
            _Pragma("unroll") \
            for (int half = 0; half < 2; half++) { \
                const int nt = p * 2 + half, o = half * 2; \
                _Pragma("unroll") \
                for (int mt = 0; mt < 2; mt++) { \
                    MMA16816(acc[mt][nt], aH[mt], bH[o], bH[o + 1]); \
                    MMA16816(acc[mt][nt], aH[mt], bL[o], bL[o + 1]); \
                    MMA16816(acc[mt][nt], aL[mt], bH[o], bH[o + 1]); \
                } \
            } \
        } \
    }

// ---------------- FFN1 ----------------
__global__ void __launch_bounds__(256, 2)
k_ffn1(const float* __restrict__ flat,
       const float* __restrict__ w1,
       const float* __restrict__ b1) {
    const int e = blockIdx.z;
    const int n = g_cnt[e];
    const int row0 = blockIdx.x * 128;
    if (row0 >= n) return;
    const int c0 = blockIdx.y * 128;

    extern __shared__ unsigned char dsm[];
    __shared__ int s_pid[128];
    __shared__ int s_tok[128];

    const int tid  = threadIdx.x;
    const int lane = tid & 31;
    const int wrp  = tid >> 5;
    const int wm   = wrp & 3;
    const int wn   = wrp >> 2;

    if (tid < 128) {
        int slot = row0 + tid;
        int pid  = (slot < n) ? g_list[e * TOKENS + slot] : -1;
        s_pid[tid] = pid;
        s_tok[tid] = (pid >= 0) ? (pid >> 2) : 0;
    }
    __syncthreads();

    const int srow = tid >> 1, sseg = tid & 1;
    const uint32_t soff = (uint32_t)srow * ROWB + (uint32_t)sseg * 32;
    const float* myA = flat + (size_t)s_tok[srow] * HD + sseg * 16;
    const float* myB = w1 + (size_t)e * GU * HD + (size_t)(c0 + srow) * HD + sseg * 16;

    const uint32_t u0 = smem_u32(dsm);
    const uint32_t aoffs = (uint32_t)(wm * 32 + (lane & 15)) * ROWB + ((lane >> 4) & 1) * 16;
    const uint32_t boffs = (uint32_t)(wn * 64 + ((lane >> 4) & 1) * 8 + (lane & 7)) * ROWB
                         + ((lane >> 3) & 1) * 16;

    float acc[2][8][4];
    #pragma unroll
    for (int mt = 0; mt < 2; mt++)
        #pragma unroll
        for (int nt = 0; nt < 8; nt++)
            #pragma unroll
            for (int q = 0; q < 4; q++) acc[mt][nt][q] = 0.f;

    // stage iter 0 into buffer 0
    stage16(myA, dsm + 0 * REG, dsm + 1 * REG, soff);
    stage16(myB, dsm + 2 * REG, dsm + 3 * REG, soff);
    __syncthreads();

    for (int it = 0; it < KIT1; it++) {
        const uint32_t cb = (uint32_t)(it & 1) * BUFB;
        unsigned char* nb = dsm + ((it & 1) ^ 1) * BUFB;
        const bool more = (it + 1 < KIT1);

        float4 pa[4], pb[4];
        if (more) {
            const float4* a4 = (const float4*)(myA + (it + 1) * BK);
            const float4* b4 = (const float4*)(myB + (it + 1) * BK);
            #pragma unroll
            for (int q = 0; q < 4; q++) { pa[q] = a4[q]; pb[q] = b4[q]; }
        }

        MMA_BODY(u0, cb, aoffs, boffs, acc);

        if (more) {
            store_split(pa, nb + 0 * REG, nb + 1 * REG, soff);
            store_split(pb, nb + 2 * REG, nb + 3 * REG, soff);
            __syncthreads();
        }
    }

    // epilogue: bias + clamp + gated activation -> g_act
    const float* b1g = b1 + (size_t)e * GU + c0;
    const int i0 = c0 >> 1;
    const int l4 = lane >> 2, lm = lane & 3;
    #pragma unroll
    for (int mt = 0; mt < 2; mt++) {
        const int mA = wm * 32 + mt * 16 + l4;
        const int pid0 = s_pid[mA], pid1 = s_pid[mA + 8];
        float* a0 = g_act + (size_t)(pid0 < 0 ? 0 : pid0) * I_DIM;
        float* a1 = g_act + (size_t)(pid1 < 0 ? 0 : pid1) * I_DIM;
        #pragma unroll
        for (int nt = 0; nt < 8; nt++) {
            const int nbase = wn * 64 + nt * 8 + 2 * lm;
            float2 bb = *(const float2*)(b1g + nbase);
            const int ii = i0 + (nbase >> 1);
            {
                float gate = acc[mt][nt][0] + bb.x;
                float up   = acc[mt][nt][1] + bb.y;
                gate = fminf(gate, LIMIT);
                up   = fminf(fmaxf(up, -LIMIT), LIMIT);
                float sg = 1.f / (1.f + __expf(-ALPHA * gate));
                if (pid0 >= 0) a0[ii] = (up + 1.f) * (gate * sg);
            }
            {
                float gate = acc[mt][nt][2] + bb.x;
                float up   = acc[mt][nt][3] + bb.y;
                gate = fminf(gate, LIMIT);
                up   = fminf(fmaxf(up, -LIMIT), LIMIT);
                float sg = 1.f / (1.f + __expf(-ALPHA * gate));
                if (pid1 >= 0) a1[ii] = (up + 1.f) * (gate * sg);
            }
        }
    }
}

// ---------------- FFN2 ----------------
__global__ void __launch_bounds__(256, 2)
k_ffn2(const float* __restrict__ w2) {
    const int e = blockIdx.z;
    const int n = g_cnt[e];
    const int row0 = blockIdx.x * 128;
    if (row0 >= n) return;
    const int h0 = blockIdx.y * 128;

    extern __shared__ unsigned char dsm[];
    __shared__ int s_pid[128];

    const int tid  = threadIdx.x;
    const int lane = tid & 31;
    const int wrp  = tid >> 5;
    const int wm   = wrp & 3;
    const int wn   = wrp >> 2;

    if (tid < 128) {
        int slot = row0 + tid;
        s_pid[tid] = (slot < n) ? g_list[e * TOKENS + slot] : -1;
    }
    __syncthreads();

    const int srow = tid >> 1, sseg = tid & 1;
    const uint32_t soff = (uint32_t)srow * ROWB + (uint32_t)sseg * 32;
    const int apid = (s_pid[srow] < 0) ? 0 : s_pid[srow];
    const float* myA = g_act + (size_t)apid * I_DIM + sseg * 16;
    const int bcol = h0 + srow;
    const bool bok = (bcol < HD);
    const float* myB = w2 + (size_t)e * HD * I_DIM + (size_t)(bok ? bcol : 0) * I_DIM + sseg * 16;

    const uint32_t u0 = smem_u32(dsm);
    const uint32_t aoffs = (uint32_t)(wm * 32 + (lane & 15)) * ROWB + ((lane >> 4) & 1) * 16;
    const uint32_t boffs = (uint32_t)(wn * 64 + ((lane >> 4) & 1) * 8 + (lane & 7)) * ROWB
                         + ((lane >> 3) & 1) * 16;

    float acc[2][8][4];
    #pragma unroll
    for (int mt = 0; mt < 2; mt++)
        #pragma unroll
        for (int nt = 0; nt < 8; nt++)
            #pragma unroll
            for (int q = 0; q < 4; q++) acc[mt][nt][q] = 0.f;

    // pre-zero B regions of both buffers for OOB cols, stage iter 0 into buffer 0
    if (!bok) {
        stage16_zero(dsm + 2 * REG, dsm + 3 * REG, soff);
        stage16_zero(dsm + BUFB + 2 * REG, dsm + BUFB + 3 * REG, soff);
    }
    stage16(myA, dsm + 0 * REG, dsm + 1 * REG, soff);
    if (bok) stage16(myB, dsm + 2 * REG, dsm + 3 * REG, soff);
    __syncthreads();

    for (int it = 0; it < KIT2; it++) {
        const uint32_t cb = (uint32_t)(it & 1) * BUFB;
        unsigned char* nb = dsm + ((it & 1) ^ 1) * BUFB;
        const bool more = (it + 1 < KIT2);

        float4 pa[4], pb[4];
        if (more) {
            const float4* a4 = (const float4*)(myA + (it + 1) * BK);
            #pragma unroll
            for (int q = 0; q < 4; q++) pa[q] = a4[q];
            if (bok) {
                const float4* b4 = (const float4*)(myB + (it + 1) * BK);
                #pragma unroll
                for (int q = 0; q < 4; q++) pb[q] = b4[q];
            }
        }

        MMA_BODY(u0, cb, aoffs, boffs, acc);

        if (more) {
            store_split(pa, nb + 0 * REG, nb + 1 * REG, soff);
            if (bok) store_split(pb, nb + 2 * REG, nb + 3 * REG, soff);
            __syncthreads();
        }
    }

    const int l4 = lane >> 2, lm = lane & 3;
    #pragma unroll
    for (int mt = 0; mt < 2; mt++) {
        const int mA = wm * 32 + mt * 16 + l4;
        const int pid0 = s_pid[mA], pid1 = s_pid[mA + 8];
        float* o0 = g_outp + (size_t)(pid0 < 0 ? 0 : pid0) * HD;
        float* o1 = g_outp + (size_t)(pid1 < 0 ? 0 : pid1) * HD;
        #pragma unroll
        for (int nt = 0; nt < 8; nt++) {
            const int ng = h0 + wn * 64 + nt * 8 + 2 * lm;
            if (ng < HD) {
                if (pid0 >= 0) { o0[ng] = acc[mt][nt][0]; o0[ng + 1] = acc[mt][nt][1]; }
                if (pid1 >= 0) { o1[ng] = acc[mt][nt][2]; o1[ng + 1] = acc[mt][nt][3]; }
            }
        }
    }
}

// ---------------- combine ----------------
__global__ void k_combine(const float* __restrict__ b2, float* __restrict__ out) {
    int t = blockIdx.x;
    __shared__ int   se[TOPK];
    __shared__ float sp[TOPK];
    if (threadIdx.x < TOPK) {
        se[threadIdx.x] = g_pe[t * TOPK + threadIdx.x];
        sp[threadIdx.x] = g_pp[t * TOPK + threadIdx.x];
    }
    __syncthreads();
    for (int h = threadIdx.x; h < HD; h += blockDim.x) {
        float s = 0.f;
        #pragma unroll
        for (int k = 0; k < TOPK; k++)
            s += sp[k] * (g_outp[(size_t)(t * TOPK + k) * HD + h] + b2[(size_t)se[k] * HD + h]);
        out[(size_t)t * HD + h] = s;
    }
}

extern "C" void kernel_launch(void* const* d_in, const int* in_sizes, int n_in,
                              void* d_out, int out_size) {
    const float* hidden = (const float*)d_in[0];
    const float* rw     = (const float*)d_in[1];
    const float* rb     = (const float*)d_in[2];
    const float* w1     = (const float*)d_in[3];
    const float* b1     = (const float*)d_in[4];
    const float* w2     = (const float*)d_in[5];
    const float* b2     = (const float*)d_in[6];
    float* out = (float*)d_out;

    cudaFuncSetAttribute(k_ffn1, cudaFuncAttributeMaxDynamicSharedMemorySize, SMEM_TOT);
    cudaFuncSetAttribute(k_ffn2, cudaFuncAttributeMaxDynamicSharedMemorySize, SMEM_TOT);

    k_init<<<1, E_NUM>>>();
    k_router<<<TOKENS, 128>>>(hidden, rw, rb);

    dim3 g1(TOKENS / 128, GU / 128, E_NUM);          // 8 x 45 x 16
    k_ffn1<<<g1, 256, SMEM_TOT>>>(hidden, w1, b1);

    dim3 g2(TOKENS / 128, (HD + 127) / 128, E_NUM);  // 8 x 23 x 16
    k_ffn2<<<g2, 256, SMEM_TOT>>>(w2);

    k_combine<<<TOKENS, 256>>>(b2, out);
}